// round 5
// baseline (speedup 1.0000x reference)
#include <cuda_runtime.h>

#define GRID_N 32
#define CELLS  1024
#define PW     34               // padded width (halo of INF)
#define PAD    (PW * PW)        // 1156
#define HALF_T 512              // threads per sub-block (one batch each)
#define NT     1024             // 2 batches per CTA
#define ESW    4                // sweeps per termination check

// named barrier over one half (ids 1,2; __syncthreads uses 0 only pre-split)
__device__ __forceinline__ void half_bar(int half) {
    asm volatile("bar.sync %0, %1;" :: "r"(half + 1), "r"(HALF_T) : "memory");
}

__global__ void __launch_bounds__(NT, 1)
dijkstra_grid_kernel(const float* __restrict__ wg, float* __restrict__ out,
                     int nbatch)
{
    __shared__ float dist[2][PAD];
    __shared__ unsigned short pred[2][CELLS];
    __shared__ unsigned char  mark[2][CELLS];
    __shared__ int flags[2][3];

    const int t    = threadIdx.x;
    const int half = t >> 9;                // 0 or 1
    const int tt   = t & (HALF_T - 1);      // 0..511 within half
    const int b    = blockIdx.x * 2 + half;
    const float INF = __int_as_float(0x7f800000);

    // full-block init (uses bar 0 once, strictly before any named barrier)
    for (int i = tt; i < PAD; i += HALF_T) dist[half][i] = INF;
    for (int i = tt; i < CELLS; i += HALF_T) mark[half][i] = 0;
    if (tt < 3) flags[half][tt] = 0;
    __syncthreads();

    if (b >= nbatch) return;                 // idle half: no shared barriers

    volatile float* vs = dist[half];

    const int x  = tt & 31;                  // lane = column
    const int y0 = (tt >> 5) * 2;            // warp owns rows y0, y0+1
    const float w0 = wg[(size_t)b * CELLS + y0 * GRID_N + x];
    const float w1 = wg[(size_t)b * CELLS + (y0 + 1) * GRID_N + x];

    float d0 = (tt == 0) ? 0.0f : INF;
    float d1 = INF;
    const int p0 = (y0 + 1) * PW + (x + 1);
    dist[half][p0] = d0;
    dist[half][p0 + PW] = d1;
    half_bar(half);

    // ---- chaotic min-plus relaxation (per half, decoupled loops) ----
    // Exact monotone-decreasing float path-sums; unique fixed point equals
    // the reference Dijkstra distances bitwise.
    int e = 0;
    for (;; e++) {
        int ch = 0;
#pragma unroll
        for (int k = 0; k < ESW; k++) {
            float ul = vs[p0 - PW - 1];
            float uc = vs[p0 - PW];
            float ur = vs[p0 - PW + 1];
            float l0 = vs[p0 - 1];
            float r0 = vs[p0 + 1];
            float l1 = vs[p0 + PW - 1];
            float r1 = vs[p0 + PW + 1];
            float bl = vs[p0 + 2 * PW - 1];
            float bc = vs[p0 + 2 * PW];
            float br = vs[p0 + 2 * PW + 1];

            float m0 = fminf(fminf(fminf(ul, uc), fminf(ur, l0)),
                             fminf(fminf(r0, l1), fminf(r1, d1))) + w0;
            if (m0 < d0) { d0 = m0; vs[p0] = m0; ch = 1; }

            float m1 = fminf(fminf(fminf(l0, r0), fminf(d0, l1)),
                             fminf(fminf(r1, bl), fminf(bc, br))) + w1;
            if (m1 < d1) { d1 = m1; vs[p0 + PW] = m1; ch = 1; }

            float m0b = d1 + w0;               // upward reg-GS hop
            if (m0b < d0) { d0 = m0b; vs[p0] = m0b; ch = 1; }
        }
        if (ch) flags[half][e % 3] = 1;
        if (tt == 0) flags[half][(e + 1) % 3] = 0; // reset ordered by barriers
        half_bar(half);
        if (!flags[half][e % 3]) break;            // uniform within half
    }

    // ---- predecessor = argmin over 8 neighbor distances (unique a.s.) ----
#pragma unroll
    for (int r = 0; r < 2; r++) {
        const int p = p0 + r * PW;
        const int cell = (y0 + r) * GRID_N + x;
        const int dy[8] = {-1, 1, 0, 0, -1, -1, 1, 1};
        const int dx[8] = { 0, 0,-1, 1, -1,  1,-1, 1};
        float bd = INF; int bi = 0;
#pragma unroll
        for (int k = 0; k < 8; k++) {
            float dd = dist[half][p + dy[k] * PW + dx[k]];
            if (dd < bd) { bd = dd; bi = (y0 + r + dy[k]) * GRID_N + (x + dx[k]); }
        }
        pred[half][cell] = (unsigned short)bi;
    }
    half_bar(half);

    // ---- backtrack from (31,31); pred chain strictly decreases dist ----
    if (tt == 0) {
        int cur = CELLS - 1;
        for (int i = 0; i < CELLS; i++) {
            mark[half][cur] = 1;
            if (cur == 0) break;
            cur = pred[half][cur];
        }
    }
    half_bar(half);

    // ---- coalesced output: 2 cells per thread ----
    float* ob = out + (size_t)b * CELLS;
    {
        const int c0 = y0 * GRID_N + x;
        ob[c0] = mark[half][c0] ? 1.0f : 0.0f;
        const int c1 = c0 + GRID_N;
        ob[c1] = mark[half][c1] ? 1.0f : 0.0f;
    }
}

extern "C" void kernel_launch(void* const* d_in, const int* in_sizes, int n_in,
                              void* d_out, int out_size)
{
    const float* w = (const float*)d_in[0];
    float* out = (float*)d_out;
    int batches = in_sizes[0] / CELLS;        // 128
    int blocks = (batches + 1) / 2;           // 64
    dijkstra_grid_kernel<<<blocks, NT>>>(w, out, batches);
}

// round 6
// speedup vs baseline: 1.2220x; 1.2220x over previous
#include <cuda_runtime.h>

#define GRID_N 32
#define CELLS  1024
#define PW     34               // padded width (halo of INF)
#define PAD    (PW * PW)
#define NT     512              // 16 warps, warp owns rows 2w, 2w+1
#define ESW    4                // sweeps per termination check
#define M      0xffffffffu

__global__ void __launch_bounds__(NT, 1)
dijkstra_grid_kernel(const float* __restrict__ wg, float* __restrict__ out)
{
    __shared__ float dist[PAD];
    __shared__ unsigned short pred[CELLS];
    __shared__ unsigned char  mark[CELLS];
    __shared__ int flags[3];

    volatile float* vs = dist;

    const int b = blockIdx.x;
    const int t = threadIdx.x;
    const int x = t & 31;
    const int y0 = (t >> 5) * 2;
    const float INF = __int_as_float(0x7f800000);

    const float w0 = wg[(size_t)b * CELLS + y0 * GRID_N + x];
    const float w1 = wg[(size_t)b * CELLS + (y0 + 1) * GRID_N + x];

    for (int i = t; i < PAD; i += NT) dist[i] = INF;
    for (int i = t; i < CELLS; i += NT) mark[i] = 0;
    if (t < 3) flags[t] = 0;
    __syncthreads();

    float d0 = (t == 0) ? 0.0f : INF;
    float d1 = INF;
    const int p0 = (y0 + 1) * PW + (x + 1);
    dist[p0] = d0;
    dist[p0 + PW] = d1;
    __syncthreads();

    // ---- chaotic min-plus relaxation ----
    // Every candidate is (neighbor_dist + own_weight): an exact, monotone-
    // decreasing reference-attainable float path-sum. Unique fixed point ==
    // reference Dijkstra distances, bitwise. Lateral moves use register GS
    // via shuffles (rows are warp-owned); vertical/diagonal cross rows via
    // smem (cross-warp) or shuffles of the other in-strip row.
    int e = 0;
    for (;; e++) {
        const float s0 = d0, s1 = d1;
#pragma unroll
        for (int k = 0; k < ESW; k++) {
            // cross-warp trios (old/chaotic values)
            float ul = vs[p0 - PW - 1];
            float uc = vs[p0 - PW];
            float ur = vs[p0 - PW + 1];
            float bl = vs[p0 + 2 * PW - 1];
            float bc = vs[p0 + 2 * PW];
            float br = vs[p0 + 2 * PW + 1];

            if ((k & 1) == 0) {
                // DOWN ordering: row A then row B
                float dl = __shfl_up_sync  (M, d1, 1);
                float dr = __shfl_down_sync(M, d1, 1);
                d0 = fminf(d0, fminf(fminf(fminf(ul, uc), fminf(ur, dl)),
                                     fminf(d1, dr)) + w0);
                float al = __shfl_up_sync  (M, d0, 1);
                float ar = __shfl_down_sync(M, d0, 1);
                d1 = fminf(d1, fminf(fminf(fminf(al, d0), fminf(ar, bl)),
                                     fminf(bc, br)) + w1);
            } else {
                // UP ordering: row B then row A
                float al = __shfl_up_sync  (M, d0, 1);
                float ar = __shfl_down_sync(M, d0, 1);
                d1 = fminf(d1, fminf(fminf(fminf(al, d0), fminf(ar, bl)),
                                     fminf(bc, br)) + w1);
                float dl = __shfl_up_sync  (M, d1, 1);
                float dr = __shfl_down_sync(M, d1, 1);
                d0 = fminf(d0, fminf(fminf(fminf(ul, uc), fminf(ur, dl)),
                                     fminf(d1, dr)) + w0);
            }

            // lateral register-GS, 4 alternating steps per row, A/B interleaved
            // (boundary lanes: shfl returns own value -> candidate d+w, harmless)
            d0 = fminf(d0, __shfl_up_sync  (M, d0, 1) + w0);
            d1 = fminf(d1, __shfl_up_sync  (M, d1, 1) + w1);
            d0 = fminf(d0, __shfl_down_sync(M, d0, 1) + w0);
            d1 = fminf(d1, __shfl_down_sync(M, d1, 1) + w1);
            d0 = fminf(d0, __shfl_up_sync  (M, d0, 1) + w0);
            d1 = fminf(d1, __shfl_up_sync  (M, d1, 1) + w1);
            d0 = fminf(d0, __shfl_down_sync(M, d0, 1) + w0);
            d1 = fminf(d1, __shfl_down_sync(M, d1, 1) + w1);

            // cheap center vertical GS hops after laterals
            d1 = fminf(d1, d0 + w1);
            d0 = fminf(d0, d1 + w0);

            vs[p0]      = d0;
            vs[p0 + PW] = d1;
        }
        // termination: registers monotone-decreasing; unchanged epoch
        // everywhere => global fixed point
        if ((d0 != s0) | (d1 != s1)) flags[e % 3] = 1;
        if (t == 0) flags[(e + 1) % 3] = 0;   // reset ordered by the barriers
        __syncthreads();
        if (!flags[e % 3]) break;             // uniform exit
    }

    // ---- predecessor = argmin over 8 neighbor distances (unique a.s.) ----
#pragma unroll
    for (int r = 0; r < 2; r++) {
        const int p = p0 + r * PW;
        const int cell = (y0 + r) * GRID_N + x;
        const int dy[8] = {-1, 1, 0, 0, -1, -1, 1, 1};
        const int dx[8] = { 0, 0,-1, 1, -1,  1,-1, 1};
        float bd = INF; int bi = 0;
#pragma unroll
        for (int k = 0; k < 8; k++) {
            float dd = dist[p + dy[k] * PW + dx[k]];
            if (dd < bd) { bd = dd; bi = (y0 + r + dy[k]) * GRID_N + (x + dx[k]); }
        }
        pred[cell] = (unsigned short)bi;
    }
    __syncthreads();

    // ---- backtrack from (31,31); pred chain strictly decreases dist ----
    if (t == 0) {
        int cur = CELLS - 1;
        for (int i = 0; i < CELLS; i++) {
            mark[cur] = 1;
            if (cur == 0) break;
            cur = pred[cur];
        }
    }
    __syncthreads();

    // ---- coalesced output: 2 cells per thread ----
    float* ob = out + (size_t)b * CELLS;
    {
        const int c0 = y0 * GRID_N + x;
        ob[c0] = mark[c0] ? 1.0f : 0.0f;
        const int c1 = c0 + GRID_N;
        ob[c1] = mark[c1] ? 1.0f : 0.0f;
    }
}

extern "C" void kernel_launch(void* const* d_in, const int* in_sizes, int n_in,
                              void* d_out, int out_size)
{
    const float* w = (const float*)d_in[0];
    float* out = (float*)d_out;
    int batches = in_sizes[0] / CELLS;     // 128
    dijkstra_grid_kernel<<<batches, NT>>>(w, out);
}

// round 7
// speedup vs baseline: 1.6054x; 1.3137x over previous
#include <cuda_runtime.h>

#define GRID_N 32
#define CELLS  1024
#define SROW   24              // smem row stride: 2*SROW % 32 == 16 -> no bank conflicts
#define NROWS  34              // 32 rows + halo row above/below
#define NT     256
#define ESW    4

__global__ void __launch_bounds__(NT, 1)
dijkstra_grid_kernel(const float* __restrict__ wg, float* __restrict__ out)
{
    __shared__ float Ea[NROWS * SROW];      // even-x columns: x=2c -> col c (0..15), halo x=32 -> 16
    __shared__ float Oa[NROWS * SROW];      // odd-x columns:  x=2c-1 -> col c (x=-1 -> 0 halo)
    __shared__ unsigned short pred[CELLS];
    __shared__ unsigned char  mark[CELLS];
    __shared__ int flags[3];

    volatile float* E = Ea;
    volatile float* O = Oa;

    const int b  = blockIdx.x;
    const int t  = threadIdx.x;
    const int tx = t & 15;                  // block col 0..15
    const int ty = t >> 4;                  // block row 0..15
    const float INF = __int_as_float(0x7f800000);

    const int x0 = tx * 2, y0 = ty * 2;     // my 2x2 block: cells (y0..y0+1, x0..x0+1)
    const int rt = y0;                      // padded rows: top halo, rowA, rowC, bottom halo
    const int ra = y0 + 1;
    const int rc = y0 + 2;
    const int rb = y0 + 3;

    const float2* w2 = (const float2*)(wg + (size_t)b * CELLS);
    const float2 wAB = w2[y0 * 16 + tx];
    const float2 wCD = w2[(y0 + 1) * 16 + tx];
    const float wa = wAB.x, wb = wAB.y, wc = wCD.x, wd = wCD.y;

    for (int i = t; i < NROWS * SROW; i += NT) { Ea[i] = INF; Oa[i] = INF; }
    for (int i = t; i < CELLS; i += NT) mark[i] = 0;
    if (t < 3) flags[t] = 0;
    __syncthreads();

    float a = (t == 0) ? 0.0f : INF;        // (y0,   x0)
    float bv = INF;                          // (y0,   x0+1)
    float c = INF;                           // (y0+1, x0)
    float d = INF;                           // (y0+1, x0+1)
    Ea[ra * SROW + tx] = a;  Oa[ra * SROW + tx + 1] = bv;
    Ea[rc * SROW + tx] = c;  Oa[rc * SROW + tx + 1] = d;
    __syncthreads();

    // ---- chaotic min-plus relaxation: GS inside the 2x2 block (registers),
    // Jacobi across blocks (smem). Every candidate is d[nb] + w[cell] in RN:
    // an exact, monotone-decreasing, reference-attainable path sum. Unique
    // fixed point == reference Dijkstra distances bitwise.
    int e = 0;
    for (;; e++) {
        const float sa = a, sb = bv, sc = c, sd = d;
#pragma unroll
        for (int k = 0; k < ESW; k++) {
            // 12 conflict-free halo loads (old values), front-batched
            float tl  = O[rt * SROW + tx];       // (y0-1, x0-1)
            float tce = E[rt * SROW + tx];       // (y0-1, x0)
            float tco = O[rt * SROW + tx + 1];   // (y0-1, x0+1)
            float tre = E[rt * SROW + tx + 1];   // (y0-1, x0+2)
            float bl  = O[rb * SROW + tx];       // (y0+2, x0-1)
            float bce = E[rb * SROW + tx];       // (y0+2, x0)
            float bco = O[rb * SROW + tx + 1];   // (y0+2, x0+1)
            float bre = E[rb * SROW + tx + 1];   // (y0+2, x0+2)
            float l0  = O[ra * SROW + tx];       // (y0,   x0-1)
            float l1  = O[rc * SROW + tx];       // (y0+1, x0-1)
            float r0  = E[ra * SROW + tx + 1];   // (y0,   x0+2)
            float r1  = E[rc * SROW + tx + 1];   // (y0+1, x0+2)

            // forward Gauss-Seidel: a, b, c, d
            a  = fminf(a,  fminf(fminf(fminf(tl, tce), fminf(tco, l0)),
                                 fminf(fminf(bv, l1),  fminf(c, d))) + wa);
            bv = fminf(bv, fminf(fminf(fminf(tce, tco), fminf(tre, a)),
                                 fminf(fminf(r0, c),    fminf(d, r1))) + wb);
            c  = fminf(c,  fminf(fminf(fminf(l0, a),   fminf(bv, l1)),
                                 fminf(fminf(d, bl),   fminf(bce, bco))) + wc);
            d  = fminf(d,  fminf(fminf(fminf(a, bv),   fminf(r0, c)),
                                 fminf(fminf(r1, bce), fminf(bco, bre))) + wd);
            // backward: c, b, a (d's inputs unchanged since its update)
            c  = fminf(c,  fminf(fminf(fminf(l0, a),   fminf(bv, l1)),
                                 fminf(fminf(d, bl),   fminf(bce, bco))) + wc);
            bv = fminf(bv, fminf(fminf(fminf(tce, tco), fminf(tre, a)),
                                 fminf(fminf(r0, c),    fminf(d, r1))) + wb);
            a  = fminf(a,  fminf(fminf(fminf(tl, tce), fminf(tco, l0)),
                                 fminf(fminf(bv, l1),  fminf(c, d))) + wa);

            E[ra * SROW + tx] = a;  O[ra * SROW + tx + 1] = bv;
            E[rc * SROW + tx] = c;  O[rc * SROW + tx + 1] = d;
        }
        // registers monotone-decreasing: epoch with no change anywhere => fixed point
        if ((a != sa) | (bv != sb) | (c != sc) | (d != sd)) flags[e % 3] = 1;
        if (t == 0) flags[(e + 1) % 3] = 0;   // reset ordered by the barriers
        __syncthreads();
        if (!flags[e % 3]) break;             // uniform exit
    }

    // ---- predecessor = argmin over 8 neighbor distances (unique a.s.) ----
    {
        float tl  = Ea[rt * SROW + tx] , x_;   (void)x_;
        // reload halo (final, post-barrier values)
        tl        = Oa[rt * SROW + tx];
        float tce = Ea[rt * SROW + tx];
        float tco = Oa[rt * SROW + tx + 1];
        float tre = Ea[rt * SROW + tx + 1];
        float bl  = Oa[rb * SROW + tx];
        float bce = Ea[rb * SROW + tx];
        float bco = Oa[rb * SROW + tx + 1];
        float bre = Ea[rb * SROW + tx + 1];
        float l0  = Oa[ra * SROW + tx];
        float l1  = Oa[rc * SROW + tx];
        float r0  = Ea[ra * SROW + tx + 1];
        float r1  = Ea[rc * SROW + tx + 1];

        const int A = y0 * GRID_N + x0, B = A + 1, C = A + GRID_N, D = A + GRID_N + 1;

#define ARGMIN8(v1,i1,v2,i2,v3,i3,v4,i4,v5,i5,v6,i6,v7,i7,v8,i8, OUTCELL)      \
        {                                                                       \
            float bd = INF; int bi = 0;                                         \
            if (v1 < bd) { bd = v1; bi = i1; }                                  \
            if (v2 < bd) { bd = v2; bi = i2; }                                  \
            if (v3 < bd) { bd = v3; bi = i3; }                                  \
            if (v4 < bd) { bd = v4; bi = i4; }                                  \
            if (v5 < bd) { bd = v5; bi = i5; }                                  \
            if (v6 < bd) { bd = v6; bi = i6; }                                  \
            if (v7 < bd) { bd = v7; bi = i7; }                                  \
            if (v8 < bd) { bd = v8; bi = i8; }                                  \
            pred[OUTCELL] = (unsigned short)bi;                                 \
        }

        ARGMIN8(tl, A-33, tce, A-32, tco, A-31, l0, A-1, bv, A+1,
                l1, A+31, c, A+32, d, A+33, A)
        ARGMIN8(tce, B-33, tco, B-32, tre, B-31, a, B-1, r0, B+1,
                c, B+31, d, B+32, r1, B+33, B)
        ARGMIN8(l0, C-33, a, C-32, bv, C-31, l1, C-1, d, C+1,
                bl, C+31, bce, C+32, bco, C+33, C)
        ARGMIN8(a, D-33, bv, D-32, r0, D-31, c, D-1, r1, D+1,
                bce, D+31, bco, D+32, bre, D+33, D)
#undef ARGMIN8
    }
    __syncthreads();

    // ---- backtrack from (31,31); pred chain strictly decreases dist ----
    if (t == 0) {
        int cur = CELLS - 1;
        for (int i = 0; i < CELLS; i++) {
            mark[cur] = 1;
            if (cur == 0) break;
            cur = pred[cur];
        }
    }
    __syncthreads();

    // ---- coalesced float2 output ----
    {
        float2* o2 = (float2*)(out + (size_t)b * CELLS);
        const int A = y0 * GRID_N + x0;
        o2[y0 * 16 + tx]       = make_float2(mark[A]      ? 1.0f : 0.0f,
                                             mark[A + 1]  ? 1.0f : 0.0f);
        o2[(y0 + 1) * 16 + tx] = make_float2(mark[A + 32] ? 1.0f : 0.0f,
                                             mark[A + 33] ? 1.0f : 0.0f);
    }
}

extern "C" void kernel_launch(void* const* d_in, const int* in_sizes, int n_in,
                              void* d_out, int out_size)
{
    const float* w = (const float*)d_in[0];
    float* out = (float*)d_out;
    int batches = in_sizes[0] / CELLS;     // 128
    dijkstra_grid_kernel<<<batches, NT>>>(w, out);
}